// round 16
// baseline (speedup 1.0000x reference)
#include <cuda_runtime.h>
#include <cuda_bf16.h>
#include <cstdint>

#define VOCAB 50257
#define EMBED 128
#define BATCH 64
#define NSENT 50
#define TC 20

#define TILE_M 128
#define NBLK ((VOCAB + TILE_M - 1) / TILE_M)   // 393

#define ROWB 272          // bf16 U row stride (17 x 16B, ldmatrix conflict-free)
#define ROWF 528          // fp32 A row stride (132 floats, LDS.64 low-conflict)

// GEMM smem layout (bytes)
#define SM_A    0                            // 128 x 528 fp32 = 67584
#define SM_UHI  (SM_A + TILE_M * ROWF)       // 67584
#define SM_ULO  (SM_UHI + BATCH * ROWB)      // 84992
#define SM_BIAS (SM_ULO + BATCH * ROWB)      // 102400
#define SM_MB   (SM_BIAS + 512)              // 102912
#define SM_TOT  (SM_MB + 16)                 // 102928 -> 2 CTAs/SM

// fused kernel smem (floats)
#define FS_M 0
#define FS_C (NSENT * EMBED)
#define FS_U (FS_C + NSENT * EMBED)
#define FS_SC (FS_U + EMBED)
#define FS_OS (FS_SC + 64)
#define FS_TOTF (FS_OS + 4 * EMBED)
#define FS_TOTB (FS_TOTF * 4)               // 54016 B

// u after hops, bf16 hi/lo, PADDED GEMM smem image: 64 rows x 272B
__device__ uint4 g_upadh4[BATCH * ROWB / 16];
__device__ uint4 g_upadl4[BATCH * ROWB / 16];

// ---------------------------------------------------------------------------
// helpers
// ---------------------------------------------------------------------------
__device__ __forceinline__ uint32_t smem_u32(const void* p) {
    uint32_t a;
    asm("{ .reg .u64 t; cvta.to.shared.u64 t, %1; cvt.u32.u64 %0, t; }"
        : "=r"(a) : "l"(p));
    return a;
}
__device__ __forceinline__ void ldsm_x4(uint32_t& r0, uint32_t& r1,
                                        uint32_t& r2, uint32_t& r3, uint32_t a) {
    asm volatile("ldmatrix.sync.aligned.m8n8.x4.shared.b16 {%0,%1,%2,%3}, [%4];"
                 : "=r"(r0), "=r"(r1), "=r"(r2), "=r"(r3) : "r"(a));
}
__device__ __forceinline__ void mma16816(float* d, const uint32_t* a,
                                         const uint32_t* b) {
    asm volatile(
        "mma.sync.aligned.m16n8k16.row.col.f32.bf16.bf16.f32 "
        "{%0,%1,%2,%3}, {%4,%5,%6,%7}, {%8,%9}, {%0,%1,%2,%3};"
        : "+f"(d[0]), "+f"(d[1]), "+f"(d[2]), "+f"(d[3])
        : "r"(a[0]), "r"(a[1]), "r"(a[2]), "r"(a[3]), "r"(b[0]), "r"(b[1]));
}
__device__ __forceinline__ uint32_t packbf(__nv_bfloat16 lo, __nv_bfloat16 hi) {
    return ((uint32_t)__bfloat16_as_ushort(hi) << 16)
         | (uint32_t)__bfloat16_as_ushort(lo);
}
__device__ __forceinline__ void split1(float x, __nv_bfloat16& h, __nv_bfloat16& l) {
    h = __float2bfloat16_rn(x);
    l = __float2bfloat16_rn(x - __bfloat162float(h));
}
// on-the-fly W split: hi = truncation (exact residual), one PRMT per pair
__device__ __forceinline__ uint32_t hi2(float a, float b) {
    return __byte_perm(__float_as_uint(a), __float_as_uint(b), 0x7632);
}
__device__ __forceinline__ uint32_t lo2(float a, float b) {
    float ra = a - __uint_as_float(__float_as_uint(a) & 0xFFFF0000u);
    float rb = b - __uint_as_float(__float_as_uint(b) & 0xFFFF0000u);
    uint32_t r;
    asm("cvt.rn.bf16x2.f32 %0, %1, %2;" : "=r"(r) : "f"(rb), "f"(ra));
    return r;   // low half = bf16(ra), matching memory order
}
#define MBAR_INIT(a, c) \
    asm volatile("mbarrier.init.shared.b64 [%0], %1;" :: "r"(a), "r"(c) : "memory")
#define MBAR_EXPECT(a, n) \
    asm volatile("mbarrier.arrive.expect_tx.shared.b64 _, [%0], %1;" \
                 :: "r"(a), "r"(n) : "memory")
#define BULK_G2S(dst, src, sz, mb) \
    asm volatile("cp.async.bulk.shared::cta.global.mbarrier::complete_tx::bytes " \
                 "[%0], [%1], %2, [%3];" \
                 :: "r"(dst), "l"(src), "r"(sz), "r"(mb) : "memory")
__device__ __forceinline__ void mbar_wait(uint32_t addr, uint32_t ph) {
    asm volatile(
        "{\n\t.reg .pred P;\n"
        "W%=:\n\t"
        "mbarrier.try_wait.parity.shared.b64 P, [%0], %1;\n\t"
        "@!P bra W%=;\n\t}"
        :: "r"(addr), "r"(ph) : "memory");
}

// ---------------------------------------------------------------------------
// Kernel 1 (FUSED, 512 threads): embeddings + 3 hops. (unchanged)
// ---------------------------------------------------------------------------
__global__ void __launch_bounds__(512, 1) fused_kernel(
        const int* __restrict__ stories,
        const int* __restrict__ questions,
        const int* __restrict__ masks,
        const float4* __restrict__ WA4,
        const float4* __restrict__ WB4,
        const float4* __restrict__ WC4,
        const float4* __restrict__ WAT4,
        const float4* __restrict__ WCT4) {
    extern __shared__ float fsm[];
    float* m_s = fsm + FS_M;
    float* c_s = fsm + FS_C;
    float* u_s = fsm + FS_U;
    float* sc  = fsm + FS_SC;
    float* os  = fsm + FS_OS;

    int b = blockIdx.x;
    int tid = threadIdx.x;
    int w = tid >> 5, lane = tid & 31;

    for (int s = w; s < NSENT; s += 16) {
        int tk_l = 0, mz = 1;
        if (lane < TC) {
            tk_l = stories[(b * NSENT + s) * TC + lane];
            mz = masks[(b * NSENT + s) * TC + lane];
        }
        unsigned bal = __ballot_sync(0xffffffffu, (lane < TC) && (mz == 0));
        int te = bal ? (s + 1) : 0;
        float4 ma = WAT4[te * 32 + lane];
        float4 ca = WCT4[te * 32 + lane];
#pragma unroll
        for (int c0 = 0; c0 < TC; c0 += 10) {
            float4 ab[10], cb2[10];
#pragma unroll
            for (int i = 0; i < 10; ++i) {
                int tk = __shfl_sync(0xffffffffu, tk_l, c0 + i);
                ab[i]  = __ldg(&WA4[tk * 32 + lane]);
                cb2[i] = __ldg(&WC4[tk * 32 + lane]);
            }
#pragma unroll
            for (int i = 0; i < 10; ++i) {
                ma.x += ab[i].x;  ma.y += ab[i].y;  ma.z += ab[i].z;  ma.w += ab[i].w;
                ca.x += cb2[i].x; ca.y += cb2[i].y; ca.z += cb2[i].z; ca.w += cb2[i].w;
            }
        }
        ((float4*)m_s)[s * 32 + lane] = ma;
        ((float4*)c_s)[s * 32 + lane] = ca;
    }
    if (w == 15) {
        int tk_l = (lane < TC) ? questions[b * TC + lane] : 0;
        float4 ua = make_float4(0.f, 0.f, 0.f, 0.f);
#pragma unroll
        for (int c0 = 0; c0 < TC; c0 += 10) {
            float4 qb[10];
#pragma unroll
            for (int i = 0; i < 10; ++i) {
                int tk = __shfl_sync(0xffffffffu, tk_l, c0 + i);
                qb[i] = __ldg(&WB4[tk * 32 + lane]);
            }
#pragma unroll
            for (int i = 0; i < 10; ++i) {
                ua.x += qb[i].x; ua.y += qb[i].y; ua.z += qb[i].z; ua.w += qb[i].w;
            }
        }
        ((float4*)u_s)[lane] = ua;
    }
    __syncthreads();

    const int gstart[4] = {0, 13, 26, 38};
    const int gend[4]   = {13, 26, 38, 50};
    int grp = tid >> 7;
    int d = tid & 127;

    for (int hop = 0; hop < 3; ++hop) {
        for (int s = w; s < NSENT; s += 16) {
            float p = 0.f;
#pragma unroll
            for (int j = 0; j < 4; ++j) {
                int dd = lane + 32 * j;
                p += m_s[s * EMBED + dd] * u_s[dd];
            }
#pragma unroll
            for (int off = 16; off; off >>= 1)
                p += __shfl_down_sync(0xffffffffu, p, off);
            if (lane == 0) sc[s] = p;
        }
        __syncthreads();
        if (w == 0) {
            float x0 = sc[lane];
            float x1 = (lane + 32 < NSENT) ? sc[lane + 32] : -1e30f;
            float mx = fmaxf(x0, x1);
#pragma unroll
            for (int off = 16; off; off >>= 1)
                mx = fmaxf(mx, __shfl_xor_sync(0xffffffffu, mx, off));
            float e0 = expf(x0 - mx);
            float e1 = (lane + 32 < NSENT) ? expf(x1 - mx) : 0.f;
            float sm = e0 + e1;
#pragma unroll
            for (int off = 16; off; off >>= 1)
                sm += __shfl_xor_sync(0xffffffffu, sm, off);
            float inv = 1.f / sm;
            sc[lane] = e0 * inv;
            if (lane + 32 < NSENT) sc[lane + 32] = e1 * inv;
        }
        __syncthreads();
        {
            float o = 0.f;
            for (int s = gstart[grp]; s < gend[grp]; ++s)
                o += c_s[s * EMBED + d] * sc[s];
            os[grp * EMBED + d] = o;
        }
        __syncthreads();
        if (tid < EMBED) {
            u_s[tid] += os[tid] + os[EMBED + tid]
                      + os[2 * EMBED + tid] + os[3 * EMBED + tid];
        }
        __syncthreads();
    }

    if (tid < 64) {
        float a = u_s[2 * tid], c = u_s[2 * tid + 1];
        __nv_bfloat16 ah, al, ch, cl;
        split1(a, ah, al);
        split1(c, ch, cl);
        ((uint32_t*)g_upadh4)[b * (ROWB / 4) + tid] = packbf(ah, ch);
        ((uint32_t*)g_upadl4)[b * (ROWB / 4) + tid] = packbf(al, cl);
    }
}

// ---------------------------------------------------------------------------
// Kernel 2 (v8): GEMM, NO convert phase. W stays fp32 in smem (per-row
// bulk copies into 528B-padded rows, all 64KB in flight at once); bf16
// hi/lo A-fragments built on the fly in the mainloop (PRMT truncation
// split, exact residual). B = pre-split bf16 U via ldmatrix (unchanged).
// ---------------------------------------------------------------------------
__global__ void __launch_bounds__(256, 2) linear_mma_kernel(
        const float* __restrict__ W,
        const float* __restrict__ bias,
        float* __restrict__ out) {
    extern __shared__ char smem[];
    const uint32_t sbase = smem_u32(smem);
    int tid = threadIdx.x;
    int w = tid >> 5, lane = tid & 31;
    int wm = w >> 1, wn = w & 1;
    int v0 = blockIdx.x * TILE_M;
    int nrows = VOCAB - v0;
    if (nrows > TILE_M) nrows = TILE_M;
    bool fullTile = (nrows == TILE_M);

    uint32_t mb = sbase + SM_MB;
    if (tid == 0) MBAR_INIT(mb, 1);
    __syncthreads();

    // tail CTA: zero A region first (bulk skips OOB rows)
    if (!fullTile) {
        float* az = (float*)(smem + SM_A);
        for (int i = tid; i < TILE_M * ROWF / 4; i += 256) az[i] = 0.f;
        __syncthreads();
    }

    // ---- stage: 1 bulk per W row (threads 0..127) + 2 bulks for U ----
    if (tid == 0)
        MBAR_EXPECT(mb, nrows * 512 + 2 * BATCH * ROWB);
    if (tid < TILE_M && tid < nrows)
        BULK_G2S(sbase + SM_A + tid * ROWF,
                 (const char*)W + (size_t)(v0 + tid) * 512, 512, mb);
    if (tid == 128)
        BULK_G2S(sbase + SM_UHI, (const char*)g_upadh4, BATCH * ROWB, mb);
    if (tid == 129)
        BULK_G2S(sbase + SM_ULO, (const char*)g_upadl4, BATCH * ROWB, mb);

    // bias (guarded LDG) overlaps the wait
    if (tid < TILE_M) {
        int gv = v0 + tid;
        ((float*)(smem + SM_BIAS))[tid] = (gv < VOCAB) ? __ldg(&bias[gv]) : 0.f;
    }

    mbar_wait(mb, 0);
    __syncthreads();

    // ---- lane offsets ----
    int cc = lane & 3;                    // A fragment column group
    int arow_lo = lane >> 2;              // A fragment row within 8
    int br = (lane & 7) + ((lane & 16) ? 8 : 0);
    int bc = ((lane >> 3) & 1) * 8;
    uint32_t boff0 = (uint32_t)((32 * wn + br) * ROWB + bc * 2);
    uint32_t boff1 = boff0 + 16 * ROWB;

    const char* abase0 = smem + SM_A + (32 * wm + arow_lo) * ROWF;
    const char* abase1 = abase0 + 16 * ROWF;

    float acc[2][4][4];
#pragma unroll
    for (int mi = 0; mi < 2; ++mi)
#pragma unroll
        for (int j = 0; j < 4; ++j)
#pragma unroll
            for (int q = 0; q < 4; ++q) acc[mi][j][q] = 0.f;

#pragma unroll
    for (int ks = 0; ks < 8; ++ks) {
        int k0 = ks * 16;
        uint32_t c0b = (uint32_t)((k0 + 2 * cc) * 4);
        uint32_t c1b = c0b + 32;          // +8 cols fp32

        uint32_t AH[2][4], AL[2][4], BH[8], BL[8];
#pragma unroll
        for (int mi = 0; mi < 2; ++mi) {
            const char* ab = mi ? abase1 : abase0;
            float2 p00 = *(const float2*)(ab + c0b);
            float2 p10 = *(const float2*)(ab + 8 * ROWF + c0b);
            float2 p01 = *(const float2*)(ab + c1b);
            float2 p11 = *(const float2*)(ab + 8 * ROWF + c1b);
            AH[mi][0] = hi2(p00.x, p00.y);  AL[mi][0] = lo2(p00.x, p00.y);
            AH[mi][1] = hi2(p10.x, p10.y);  AL[mi][1] = lo2(p10.x, p10.y);
            AH[mi][2] = hi2(p01.x, p01.y);  AL[mi][2] = lo2(p01.x, p01.y);
            AH[mi][3] = hi2(p11.x, p11.y);  AL[mi][3] = lo2(p11.x, p11.y);
        }
        uint32_t k2 = (uint32_t)(ks * 32);
        ldsm_x4(BH[0], BH[1], BH[2], BH[3], sbase + SM_UHI + boff0 + k2);
        ldsm_x4(BH[4], BH[5], BH[6], BH[7], sbase + SM_UHI + boff1 + k2);
        ldsm_x4(BL[0], BL[1], BL[2], BL[3], sbase + SM_ULO + boff0 + k2);
        ldsm_x4(BL[4], BL[5], BL[6], BL[7], sbase + SM_ULO + boff1 + k2);
#pragma unroll
        for (int mi = 0; mi < 2; ++mi) {
#pragma unroll
            for (int j = 0; j < 4; ++j) {
                mma16816(acc[mi][j], AH[mi], &BH[2 * j]);   // hi*hi
                mma16816(acc[mi][j], AH[mi], &BL[2 * j]);   // hi*lo
                mma16816(acc[mi][j], AL[mi], &BH[2 * j]);   // lo*hi
            }
        }
    }

    // ---- epilogue: transpose via smem (stride 67), consecutive-v stores ----
    __syncthreads();
    {
        float* smemT = (float*)smem;          // 128 x 67 floats, reuses A region
        int mrow = lane >> 2;
        int ncol = (lane & 3) * 2;
#pragma unroll
        for (int mi = 0; mi < 2; ++mi) {
            int va = 32 * wm + 16 * mi + mrow;
            int vb = va + 8;
#pragma unroll
            for (int j = 0; j < 4; ++j) {
                int b0 = 32 * wn + 8 * j + ncol;
                smemT[va * 67 + b0]     = acc[mi][j][0];
                smemT[va * 67 + b0 + 1] = acc[mi][j][1];
                smemT[vb * 67 + b0]     = acc[mi][j][2];
                smemT[vb * 67 + b0 + 1] = acc[mi][j][3];
            }
        }
        __syncthreads();
        const float* bias_s = (const float*)(smem + SM_BIAS);
        for (int bb = w; bb < BATCH; bb += 8) {
            size_t rowbase = (size_t)bb * VOCAB;
#pragma unroll
            for (int vh = 0; vh < 4; ++vh) {
                int vl = vh * 32 + lane;
                int v = v0 + vl;
                if (v < VOCAB)
                    out[rowbase + v] = smemT[vl * 67 + bb] + bias_s[vl];
            }
        }
    }
}

// ---------------------------------------------------------------------------
extern "C" void kernel_launch(void* const* d_in, const int* in_sizes, int n_in,
                              void* d_out, int out_size) {
    const int*   stories   = (const int*)d_in[0];
    const int*   questions = (const int*)d_in[1];
    const int*   masks     = (const int*)d_in[2];
    const float* WA        = (const float*)d_in[3];
    const float* WB        = (const float*)d_in[4];
    const float* WC        = (const float*)d_in[5];
    const float* WAT       = (const float*)d_in[6];
    const float* WCT       = (const float*)d_in[7];
    const float* Wlin      = (const float*)d_in[8];
    const float* blin      = (const float*)d_in[9];
    float* out = (float*)d_out;

    cudaFuncSetAttribute(fused_kernel,
                         cudaFuncAttributeMaxDynamicSharedMemorySize, FS_TOTB);
    cudaFuncSetAttribute(linear_mma_kernel,
                         cudaFuncAttributeMaxDynamicSharedMemorySize, SM_TOT);

    fused_kernel<<<BATCH, 512, FS_TOTB>>>(stories, questions, masks,
                                          (const float4*)WA, (const float4*)WB,
                                          (const float4*)WC, (const float4*)WAT,
                                          (const float4*)WCT);
    linear_mma_kernel<<<NBLK, 256, SM_TOT>>>(Wlin, blin, out);
}